// round 2
// baseline (speedup 1.0000x reference)
#include <cuda_runtime.h>
#include <math.h>
#include <float.h>

#define NT   1024
#define MAXK 128

// Exactly replicates the reference's per-element float32 computation:
//   avg = s/200 ; sig = sqrt(-2/log(1-avg^2)) ; sig2 = sig^2  (sqrt-then-square!)
__device__ __forceinline__ float sig2_of_sum(float s) {
    float avg = s / 200.0f;
    float l   = logf(1.0f - avg * avg);
    float v   = -2.0f / l;
    float sg  = sqrtf(v);
    return sg * sg;
}

__device__ __forceinline__ void upd_minmax(float v, float& m1, float& m2,
                                           float& M1, float& M2) {
    if (v < m1) { m2 = m1; m1 = v; } else if (v < m2) { m2 = v; }
    if (v > M1) { M2 = M1; M1 = v; } else if (v > M2) { M2 = v; }
}

__global__ __launch_bounds__(NT, 1)
void ENCELDDT_67602785239182_kernel(const float* __restrict__ sigmas,
                                    const float* __restrict__ y,
                                    const float* __restrict__ py,
                                    float* __restrict__ out,
                                    int N)
{
    __shared__ float red[32][4];                    // per-warp (m1,m2,M1,M2)
    __shared__ float s_begin, s_interval, s_sigth, s_sumb, s_m1;
    __shared__ int   s_count;
    __shared__ unsigned long long s_key[MAXK];      // (idx<<32)|slot, sorted by idx
    __shared__ float s_val[MAXK];                   // sigma value per slot
    __shared__ float s_crd[MAXK][6];                // y.xyz, py.xyz per slot
    __shared__ float fb[32][3];                     // fallback block-reduce

    const int tid = threadIdx.x;
    const unsigned FULL = 0xFFFFFFFFu;
    const int N4 = N & ~3;

    // ---- Phase A: vectorized scan for 2 smallest + 2 largest sigmas ----
    float m1 = FLT_MAX, m2 = FLT_MAX, M1 = -FLT_MAX, M2 = -FLT_MAX;
    for (int i = tid * 4; i < N4; i += NT * 4) {
        float4 q = *reinterpret_cast<const float4*>(sigmas + i);
        upd_minmax(q.x, m1, m2, M1, M2);
        upd_minmax(q.y, m1, m2, M1, M2);
        upd_minmax(q.z, m1, m2, M1, M2);
        upd_minmax(q.w, m1, m2, M1, M2);
    }
    for (int i = N4 + tid; i < N; i += NT)
        upd_minmax(sigmas[i], m1, m2, M1, M2);

    #pragma unroll
    for (int off = 16; off; off >>= 1) {
        float a = __shfl_down_sync(FULL, m1, off);
        float b = __shfl_down_sync(FULL, m2, off);
        if (a < m1) { m2 = m1; m1 = a; } else if (a < m2) { m2 = a; }
        if (b < m1) { m2 = m1; m1 = b; } else if (b < m2) { m2 = b; }
        float c = __shfl_down_sync(FULL, M1, off);
        float d = __shfl_down_sync(FULL, M2, off);
        if (c > M1) { M2 = M1; M1 = c; } else if (c > M2) { M2 = c; }
        if (d > M1) { M2 = M1; M1 = d; } else if (d > M2) { M2 = d; }
    }
    if ((tid & 31) == 0) {
        red[tid >> 5][0] = m1; red[tid >> 5][1] = m2;
        red[tid >> 5][2] = M1; red[tid >> 5][3] = M2;
    }
    __syncthreads();                                               // barrier 1

    if (tid < 32) {
        m1 = red[tid][0]; m2 = red[tid][1]; M1 = red[tid][2]; M2 = red[tid][3];
        #pragma unroll
        for (int off = 16; off; off >>= 1) {
            float a = __shfl_down_sync(FULL, m1, off);
            float b = __shfl_down_sync(FULL, m2, off);
            if (a < m1) { m2 = m1; m1 = a; } else if (a < m2) { m2 = a; }
            if (b < m1) { m2 = m1; m1 = b; } else if (b < m2) { m2 = b; }
            float c = __shfl_down_sync(FULL, M1, off);
            float d = __shfl_down_sync(FULL, M2, off);
            if (c > M1) { M2 = M1; M1 = c; } else if (c > M2) { M2 = c; }
            if (d > M1) { M2 = M1; M1 = d; } else if (d > M2) { M2 = d; }
        }
        if (tid == 0) {
            // min/max off-diagonal sums (fadd commutative + monotone)
            float begin    = sig2_of_sum(M1 + M2);     // sig2 decreasing in sum
            float end      = sig2_of_sum(m1 + m2);
            float interval = (end - begin) / 10.0f;
            float sigth, sumb;
            float th = (begin + 9.0f * interval) * 0.999f;   // conservative margin
            if (th > 0.0f && interval > 0.0f) {
                float u     = -expm1f(-2.0f / th);           // 1 - exp(-2/th)
                float avg_b = sqrtf(fmaxf(u, 0.0f)) * 1.002f;
                sumb  = avg_b * 200.0f + 0.01f;              // loose sum bound
                sigth = sumb - m1;                           // per-index bound
            } else {
                sumb = FLT_MAX; sigth = FLT_MAX;             // degenerate: admit all
            }
            s_begin = begin; s_interval = interval;
            s_sigth = sigth; s_sumb = sumb; s_m1 = m1;
            s_count = 0;
        }
    }
    __syncthreads();                                               // barrier 2

    // ---- Phase B: gather candidates AND prefetch their coords into smem ----
    const float sigth = s_sigth;
    for (int i = tid * 4; i < N4; i += NT * 4) {
        float4 q = *reinterpret_cast<const float4*>(sigmas + i);   // L1 hit
        float vals[4] = {q.x, q.y, q.z, q.w};
        #pragma unroll
        for (int k = 0; k < 4; k++) {
            if (vals[k] <= sigth) {
                int p = atomicAdd(&s_count, 1);
                if (p < MAXK) {
                    int idx = i + k;
                    s_key[p] = ((unsigned long long)(unsigned)idx << 32) | (unsigned)p;
                    s_val[p] = vals[k];
                    s_crd[p][0] = y[3 * idx];     s_crd[p][1] = y[3 * idx + 1];
                    s_crd[p][2] = y[3 * idx + 2];
                    s_crd[p][3] = py[3 * idx];    s_crd[p][4] = py[3 * idx + 1];
                    s_crd[p][5] = py[3 * idx + 2];
                }
            }
        }
    }
    for (int i = N4 + tid; i < N; i += NT) {
        float v = sigmas[i];
        if (v <= sigth) {
            int p = atomicAdd(&s_count, 1);
            if (p < MAXK) {
                s_key[p] = ((unsigned long long)(unsigned)i << 32) | (unsigned)p;
                s_val[p] = v;
                s_crd[p][0] = y[3 * i];     s_crd[p][1] = y[3 * i + 1];
                s_crd[p][2] = y[3 * i + 2];
                s_crd[p][3] = py[3 * i];    s_crd[p][4] = py[3 * i + 1];
                s_crd[p][5] = py[3 * i + 2];
            }
        }
    }
    __syncthreads();                                               // barrier 3

    const int   K        = s_count;
    const float begin    = s_begin;
    const float interval = s_interval;

    if (K <= MAXK) {
        // ---- Fast path: warp 0 does sort + pair eval + reduce; rest exit ----
        if (tid >= 32) return;

        if (tid == 0) {                      // deterministic order (idx-sorted)
            for (int a = 1; a < K; a++) {
                unsigned long long kv = s_key[a];
                int b = a - 1;
                while (b >= 0 && s_key[b] > kv) { s_key[b + 1] = s_key[b]; b--; }
                s_key[b + 1] = kv;
            }
        }
        __syncwarp();

        float cnt = 0.0f, ss = 0.0f, st = 0.0f;
        int total = K * K;
        for (int p = tid; p < total; p += 32) {
            int a = p / K, b = p - a * K;
            if (a == b) continue;            // off-diagonal only
            int sa = (int)(unsigned)(s_key[a] & 0xFFFFFFFFull);
            int sb = (int)(unsigned)(s_key[b] & 0xFFFFFFFFull);
            float s    = s_val[sa] + s_val[sb];
            float sig2 = sig2_of_sum(s);
            float t    = (sig2 - begin) / interval;
            int bi = (int)floorf(t);
            bi = bi < 0 ? 0 : (bi > 9 ? 9 : bi);
            if (bi == 9) {
                float dx = s_crd[sa][0] - s_crd[sb][0];
                float dy = s_crd[sa][1] - s_crd[sb][1];
                float dz = s_crd[sa][2] - s_crd[sb][2];
                float dg = sqrtf(dx * dx + dy * dy + dz * dz);
                float ex = s_crd[sa][3] - s_crd[sb][3];
                float ey = s_crd[sa][4] - s_crd[sb][4];
                float ez = s_crd[sa][5] - s_crd[sb][5];
                float dp = sqrtf(ex * ex + ey * ey + ez * ez);
                float tr = dg - dp;
                cnt += 1.0f; ss += sig2; st += tr * tr;
            }
        }
        #pragma unroll
        for (int off = 16; off; off >>= 1) {
            cnt += __shfl_down_sync(FULL, cnt, off);
            ss  += __shfl_down_sync(FULL, ss,  off);
            st  += __shfl_down_sync(FULL, st,  off);
        }
        if (tid == 0) {
            float mvar = sqrtf(ss / cnt);    // cnt >= 2: min-sum pair is in bin 9
            float rmse = sqrtf(st / cnt);
            out[0] = fabsf(mvar - rmse) / mvar;
        }
        return;
    }

    // ---- Fallback (degenerate data, K > MAXK): exact all-pairs, all threads ----
    {
        const float sumb = s_sumb;
        float cnt = 0.0f, ss = 0.0f, st = 0.0f;
        long total = (long)N * (long)N;
        for (long p = tid; p < total; p += NT) {
            int i = (int)(p / N), j = (int)(p - (long)i * N);
            if (i == j) continue;
            float s = __ldg(sigmas + i) + __ldg(sigmas + j);
            if (s > sumb) continue;          // cannot be bin 9
            float sig2 = sig2_of_sum(s);
            float t    = (sig2 - begin) / interval;
            int bi = (int)floorf(t);
            bi = bi < 0 ? 0 : (bi > 9 ? 9 : bi);
            if (bi == 9) {
                float dx = y[3*i]   - y[3*j];
                float dy = y[3*i+1] - y[3*j+1];
                float dz = y[3*i+2] - y[3*j+2];
                float dg = sqrtf(dx*dx + dy*dy + dz*dz);
                float ex = py[3*i]   - py[3*j];
                float ey = py[3*i+1] - py[3*j+1];
                float ez = py[3*i+2] - py[3*j+2];
                float dp = sqrtf(ex*ex + ey*ey + ez*ez);
                float tr = dg - dp;
                cnt += 1.0f; ss += sig2; st += tr * tr;
            }
        }
        #pragma unroll
        for (int off = 16; off; off >>= 1) {
            cnt += __shfl_down_sync(FULL, cnt, off);
            ss  += __shfl_down_sync(FULL, ss,  off);
            st  += __shfl_down_sync(FULL, st,  off);
        }
        if ((tid & 31) == 0) { fb[tid>>5][0] = cnt; fb[tid>>5][1] = ss; fb[tid>>5][2] = st; }
        __syncthreads();
        if (tid < 32) {
            cnt = fb[tid][0]; ss = fb[tid][1]; st = fb[tid][2];
            #pragma unroll
            for (int off = 16; off; off >>= 1) {
                cnt += __shfl_down_sync(FULL, cnt, off);
                ss  += __shfl_down_sync(FULL, ss,  off);
                st  += __shfl_down_sync(FULL, st,  off);
            }
            if (tid == 0) {
                float mvar = sqrtf(ss / cnt);
                float rmse = sqrtf(st / cnt);
                out[0] = fabsf(mvar - rmse) / mvar;
            }
        }
    }
}

extern "C" void kernel_launch(void* const* d_in, const int* in_sizes, int n_in,
                              void* d_out, int out_size) {
    const float* sigmas = (const float*)d_in[0];
    const float* y      = (const float*)d_in[1];
    const float* py     = (const float*)d_in[2];
    int N = in_sizes[0];
    ENCELDDT_67602785239182_kernel<<<1, NT>>>(sigmas, y, py, (float*)d_out, N);
}

// round 3
// speedup vs baseline: 1.1628x; 1.1628x over previous
#include <cuda_runtime.h>
#include <math.h>
#include <float.h>

#define NT    512
#define EPT   8           // elements per thread (fast path covers N <= NT*EPT)
#define MAXK  128
#define GNT   1024        // generic-path threads

// Exactly replicates the reference's per-element float32 computation:
//   avg = s/200 ; sig = sqrt(-2/log(1-avg^2)) ; sig2 = sig^2  (sqrt-then-square!)
__device__ __forceinline__ float sig2_of_sum(float s) {
    float avg = s / 200.0f;
    float l   = logf(1.0f - avg * avg);
    float v   = -2.0f / l;
    float sg  = sqrtf(v);
    return sg * sg;
}

// merge (a1<=a2) with (b1<=b2) -> two smallest, in place
__device__ __forceinline__ void mrg2min(float& a1, float& a2, float b1, float b2) {
    float n1 = fminf(a1, b1);
    float n2 = fminf(fmaxf(a1, b1), fminf(a2, b2));
    a1 = n1; a2 = n2;
}
// merge (a1>=a2) with (b1>=b2) -> two largest, in place
__device__ __forceinline__ void mrg2max(float& a1, float& a2, float b1, float b2) {
    float n1 = fmaxf(a1, b1);
    float n2 = fmaxf(fminf(a1, b1), fmaxf(a2, b2));
    a1 = n1; a2 = n2;
}

// Shared threshold computation (lane-0 serial part). Returns sigth.
__device__ __forceinline__ float make_sigth(float begin, float interval, float m1) {
    float th = (begin + 9.0f * interval) * 0.999f;       // conservative margin
    if (th > 0.0f && interval > 0.0f) {
        float u     = -expm1f(-2.0f / th);               // 1 - exp(-2/th)
        float avg_b = sqrtf(fmaxf(u, 0.0f)) * 1.002f;
        float sum_b = avg_b * 200.0f + 0.01f;            // loose sum bound
        return sum_b - m1;                               // per-index bound
    }
    return FLT_MAX;                                      // degenerate: admit all
}

// ============================ FAST PATH (N <= NT*EPT) ============================
__global__ __launch_bounds__(NT, 1)
void ENCELDDT_fast(const float* __restrict__ sigmas,
                   const float* __restrict__ y,
                   const float* __restrict__ py,
                   float* __restrict__ out, int N)
{
    __shared__ float red[16][4];                 // per-warp (m1,m2,M1,M2) / reused
    __shared__ float s_begin, s_interval, s_sigth;
    __shared__ int   s_count;
    __shared__ unsigned long long s_key[MAXK];   // (idx<<32)|slot
    __shared__ float s_val[MAXK];
    __shared__ float s_crd[MAXK][6];

    const int tid = threadIdx.x;
    const unsigned FULL = 0xFFFFFFFFu;
    const int base = tid * EPT;
    const bool full = (base + EPT <= N);

    // ---- load 8 owned elements into registers ----
    float v[EPT];
    if (full) {
        float4 a = *reinterpret_cast<const float4*>(sigmas + base);
        float4 b = *reinterpret_cast<const float4*>(sigmas + base + 4);
        v[0]=a.x; v[1]=a.y; v[2]=a.z; v[3]=a.w;
        v[4]=b.x; v[5]=b.y; v[6]=b.z; v[7]=b.w;
    } else {
        #pragma unroll
        for (int k = 0; k < EPT; k++)
            v[k] = (base + k < N) ? sigmas[base + k] : 0.0f;  // guarded later
    }

    // ---- branch-free thread-local min2 / max2 (sorting-network merges) ----
    float m1, m2, M1, M2;
    {
        float lo[4], hi[4], go[4], gi[4];
        #pragma unroll
        for (int k = 0; k < 4; k++) {
            bool va = full || (base + 2*k     < N);
            bool vb = full || (base + 2*k + 1 < N);
            float a = v[2*k], b = v[2*k+1];
            float an = va ? a :  FLT_MAX, bn = vb ? b :  FLT_MAX;
            float ax = va ? a : -FLT_MAX, bx = vb ? b : -FLT_MAX;
            lo[k] = fminf(an, bn);  hi[k] = fmaxf(an, bn);   // ascending pair
            go[k] = fmaxf(ax, bx);  gi[k] = fminf(ax, bx);   // descending pair
        }
        float q1 = lo[0], q2 = hi[0]; mrg2min(q1, q2, lo[1], hi[1]);
        float r1 = lo[2], r2 = hi[2]; mrg2min(r1, r2, lo[3], hi[3]);
        mrg2min(q1, q2, r1, r2); m1 = q1; m2 = q2;
        float s1 = go[0], s2 = gi[0]; mrg2max(s1, s2, go[1], gi[1]);
        float t1 = go[2], t2 = gi[2]; mrg2max(t1, t2, go[3], gi[3]);
        mrg2max(s1, s2, t1, t2); M1 = s1; M2 = s2;
    }

    // ---- warp reduce (5 steps, 4 shfl + 8 FMNMX each) ----
    #pragma unroll
    for (int off = 16; off; off >>= 1) {
        float a1 = __shfl_down_sync(FULL, m1, off);
        float a2 = __shfl_down_sync(FULL, m2, off);
        mrg2min(m1, m2, a1, a2);
        float b1 = __shfl_down_sync(FULL, M1, off);
        float b2 = __shfl_down_sync(FULL, M2, off);
        mrg2max(M1, M2, b1, b2);
    }
    if ((tid & 31) == 0) {
        red[tid >> 5][0] = m1; red[tid >> 5][1] = m2;
        red[tid >> 5][2] = M1; red[tid >> 5][3] = M2;
    }
    __syncthreads();                                           // barrier 1

    if (tid < 32) {
        if (tid < 16) { m1 = red[tid][0]; m2 = red[tid][1]; M1 = red[tid][2]; M2 = red[tid][3]; }
        else          { m1 = FLT_MAX; m2 = FLT_MAX; M1 = -FLT_MAX; M2 = -FLT_MAX; }
        #pragma unroll
        for (int off = 8; off; off >>= 1) {
            float a1 = __shfl_down_sync(FULL, m1, off);
            float a2 = __shfl_down_sync(FULL, m2, off);
            mrg2min(m1, m2, a1, a2);
            float b1 = __shfl_down_sync(FULL, M1, off);
            float b2 = __shfl_down_sync(FULL, M2, off);
            mrg2max(M1, M2, b1, b2);
        }
        // broadcast lane-0 results; lanes 0/1 evaluate the two log chains in parallel
        float gm1 = __shfl_sync(FULL, m1, 0);
        float gm2 = __shfl_sync(FULL, m2, 0);
        float gM1 = __shfl_sync(FULL, M1, 0);
        float gM2 = __shfl_sync(FULL, M2, 0);
        float t = sig2_of_sum((tid & 1) ? (gm1 + gm2) : (gM1 + gM2));
        float begin = __shfl_sync(FULL, t, 0);     // sig2 decreasing in sum
        float end   = __shfl_sync(FULL, t, 1);
        if (tid == 0) {
            float interval = (end - begin) / 10.0f;
            s_begin = begin; s_interval = interval;
            s_sigth = make_sigth(begin, interval, gm1);
            s_count = 0;
        }
    }
    __syncthreads();                                           // barrier 2

    // ---- phase B: test registers vs threshold; gather + coord prefetch ----
    const float sigth = s_sigth;
    #pragma unroll
    for (int k = 0; k < EPT; k++) {
        int idx = base + k;
        if (v[k] <= sigth && (full || idx < N)) {
            int p = atomicAdd(&s_count, 1);
            if (p < MAXK) {
                s_key[p] = ((unsigned long long)(unsigned)idx << 32) | (unsigned)p;
                s_val[p] = v[k];
                s_crd[p][0] = __ldg(y  + 3*idx);  s_crd[p][1] = __ldg(y  + 3*idx + 1);
                s_crd[p][2] = __ldg(y  + 3*idx + 2);
                s_crd[p][3] = __ldg(py + 3*idx);  s_crd[p][4] = __ldg(py + 3*idx + 1);
                s_crd[p][5] = __ldg(py + 3*idx + 2);
            }
        }
    }
    __syncthreads();                                           // barrier 3

    const int   K        = s_count;
    const float begin    = s_begin;
    const float interval = s_interval;

    if (K <= MAXK) {
        if (tid >= 32) return;                 // warp 0 finishes alone
        if (tid == 0) {                        // deterministic order (idx-sorted)
            for (int a = 1; a < K; a++) {
                unsigned long long kv = s_key[a];
                int b = a - 1;
                while (b >= 0 && s_key[b] > kv) { s_key[b + 1] = s_key[b]; b--; }
                s_key[b + 1] = kv;
            }
        }
        __syncwarp();

        float cnt = 0.0f, ss = 0.0f, st = 0.0f;
        int total = K * K;
        for (int p = tid; p < total; p += 32) {
            int a = p / K, b = p - a * K;
            if (a == b) continue;
            int sa = (int)(unsigned)(s_key[a] & 0xFFFFFFFFull);
            int sb = (int)(unsigned)(s_key[b] & 0xFFFFFFFFull);
            float sig2 = sig2_of_sum(s_val[sa] + s_val[sb]);
            float t    = (sig2 - begin) / interval;
            int bi = (int)floorf(t);
            bi = bi < 0 ? 0 : (bi > 9 ? 9 : bi);
            if (bi == 9) {
                float dx = s_crd[sa][0] - s_crd[sb][0];
                float dy = s_crd[sa][1] - s_crd[sb][1];
                float dz = s_crd[sa][2] - s_crd[sb][2];
                float dg = sqrtf(dx*dx + dy*dy + dz*dz);
                float ex = s_crd[sa][3] - s_crd[sb][3];
                float ey = s_crd[sa][4] - s_crd[sb][4];
                float ez = s_crd[sa][5] - s_crd[sb][5];
                float dp = sqrtf(ex*ex + ey*ey + ez*ez);
                float tr = dg - dp;
                cnt += 1.0f; ss += sig2; st += tr * tr;
            }
        }
        #pragma unroll
        for (int off = 16; off; off >>= 1) {
            cnt += __shfl_down_sync(FULL, cnt, off);
            ss  += __shfl_down_sync(FULL, ss,  off);
            st  += __shfl_down_sync(FULL, st,  off);
        }
        if (tid == 0) {
            float mvar = sqrtf(ss / cnt);      // cnt >= 2: min-sum pair is bin 9
            float rmse = sqrtf(st / cnt);
            out[0] = fabsf(mvar - rmse) / mvar;
        }
        return;
    }

    // ---- degenerate fallback (K > MAXK): exact all-pairs, all threads ----
    {
        float cnt = 0.0f, ss = 0.0f, st = 0.0f;
        long total = (long)N * (long)N;
        for (long p = tid; p < total; p += NT) {
            int i = (int)(p / N), j = (int)(p - (long)i * N);
            if (i == j) continue;
            float s = __ldg(sigmas + i) + __ldg(sigmas + j);
            float sig2 = sig2_of_sum(s);
            float t    = (sig2 - begin) / interval;
            int bi = (int)floorf(t);
            bi = bi < 0 ? 0 : (bi > 9 ? 9 : bi);
            if (bi == 9) {
                float dx = y[3*i]-y[3*j], dy = y[3*i+1]-y[3*j+1], dz = y[3*i+2]-y[3*j+2];
                float dg = sqrtf(dx*dx + dy*dy + dz*dz);
                float ex = py[3*i]-py[3*j], ey = py[3*i+1]-py[3*j+1], ez = py[3*i+2]-py[3*j+2];
                float dp = sqrtf(ex*ex + ey*ey + ez*ez);
                float tr = dg - dp;
                cnt += 1.0f; ss += sig2; st += tr * tr;
            }
        }
        #pragma unroll
        for (int off = 16; off; off >>= 1) {
            cnt += __shfl_down_sync(FULL, cnt, off);
            ss  += __shfl_down_sync(FULL, ss,  off);
            st  += __shfl_down_sync(FULL, st,  off);
        }
        if ((tid & 31) == 0) { red[tid>>5][0]=cnt; red[tid>>5][1]=ss; red[tid>>5][2]=st; }
        __syncthreads();
        if (tid < 32) {
            if (tid < 16) { cnt = red[tid][0]; ss = red[tid][1]; st = red[tid][2]; }
            else          { cnt = 0.0f; ss = 0.0f; st = 0.0f; }
            #pragma unroll
            for (int off = 8; off; off >>= 1) {
                cnt += __shfl_down_sync(FULL, cnt, off);
                ss  += __shfl_down_sync(FULL, ss,  off);
                st  += __shfl_down_sync(FULL, st,  off);
            }
            if (tid == 0) {
                float mvar = sqrtf(ss / cnt);
                float rmse = sqrtf(st / cnt);
                out[0] = fabsf(mvar - rmse) / mvar;
            }
        }
    }
}

// ==================== GENERIC PATH (N > NT*EPT; strided, R1-style) ====================
__device__ __forceinline__ void upd_minmax(float v, float& m1, float& m2,
                                           float& M1, float& M2) {
    if (v < m1) { m2 = m1; m1 = v; } else if (v < m2) { m2 = v; }
    if (v > M1) { M2 = M1; M1 = v; } else if (v > M2) { M2 = v; }
}

__global__ __launch_bounds__(GNT, 1)
void ENCELDDT_generic(const float* __restrict__ sigmas,
                      const float* __restrict__ y,
                      const float* __restrict__ py,
                      float* __restrict__ out, int N)
{
    __shared__ float red[32][4];
    __shared__ float s_begin, s_interval, s_sigth;
    __shared__ int   s_count;
    __shared__ unsigned long long s_key[MAXK];
    __shared__ float s_val[MAXK];

    const int tid = threadIdx.x;
    const unsigned FULL = 0xFFFFFFFFu;

    float m1 = FLT_MAX, m2 = FLT_MAX, M1 = -FLT_MAX, M2 = -FLT_MAX;
    for (int i = tid; i < N; i += GNT) upd_minmax(sigmas[i], m1, m2, M1, M2);
    #pragma unroll
    for (int off = 16; off; off >>= 1) {
        float a1 = __shfl_down_sync(FULL, m1, off);
        float a2 = __shfl_down_sync(FULL, m2, off);
        mrg2min(m1, m2, a1, a2);
        float b1 = __shfl_down_sync(FULL, M1, off);
        float b2 = __shfl_down_sync(FULL, M2, off);
        mrg2max(M1, M2, b1, b2);
    }
    if ((tid & 31) == 0) { red[tid>>5][0]=m1; red[tid>>5][1]=m2; red[tid>>5][2]=M1; red[tid>>5][3]=M2; }
    __syncthreads();
    if (tid < 32) {
        m1 = red[tid][0]; m2 = red[tid][1]; M1 = red[tid][2]; M2 = red[tid][3];
        #pragma unroll
        for (int off = 16; off; off >>= 1) {
            float a1 = __shfl_down_sync(FULL, m1, off);
            float a2 = __shfl_down_sync(FULL, m2, off);
            mrg2min(m1, m2, a1, a2);
            float b1 = __shfl_down_sync(FULL, M1, off);
            float b2 = __shfl_down_sync(FULL, M2, off);
            mrg2max(M1, M2, b1, b2);
        }
        if (tid == 0) {
            float begin    = sig2_of_sum(M1 + M2);
            float end      = sig2_of_sum(m1 + m2);
            float interval = (end - begin) / 10.0f;
            s_begin = begin; s_interval = interval;
            s_sigth = make_sigth(begin, interval, m1);
            s_count = 0;
        }
    }
    __syncthreads();

    const float sigth = s_sigth;
    for (int i = tid; i < N; i += GNT) {
        float v = sigmas[i];
        if (v <= sigth) {
            int p = atomicAdd(&s_count, 1);
            if (p < MAXK) {
                s_key[p] = ((unsigned long long)(unsigned)i << 32) | (unsigned)p;
                s_val[p] = v;
            }
        }
    }
    __syncthreads();

    const int K = s_count;
    const float begin = s_begin, interval = s_interval;

    if (K <= MAXK) {
        if (tid >= 32) return;
        if (tid == 0) {
            for (int a = 1; a < K; a++) {
                unsigned long long kv = s_key[a];
                int b = a - 1;
                while (b >= 0 && s_key[b] > kv) { s_key[b + 1] = s_key[b]; b--; }
                s_key[b + 1] = kv;
            }
        }
        __syncwarp();
        float cnt = 0.0f, ss = 0.0f, st = 0.0f;
        int total = K * K;
        for (int p = tid; p < total; p += 32) {
            int a = p / K, b = p - a * K;
            if (a == b) continue;
            int i = (int)(s_key[a] >> 32), j = (int)(s_key[b] >> 32);
            int sa = (int)(unsigned)(s_key[a] & 0xFFFFFFFFull);
            int sb = (int)(unsigned)(s_key[b] & 0xFFFFFFFFull);
            float sig2 = sig2_of_sum(s_val[sa] + s_val[sb]);
            float t = (sig2 - begin) / interval;
            int bi = (int)floorf(t);
            bi = bi < 0 ? 0 : (bi > 9 ? 9 : bi);
            if (bi == 9) {
                float dx = y[3*i]-y[3*j], dy = y[3*i+1]-y[3*j+1], dz = y[3*i+2]-y[3*j+2];
                float dg = sqrtf(dx*dx + dy*dy + dz*dz);
                float ex = py[3*i]-py[3*j], ey = py[3*i+1]-py[3*j+1], ez = py[3*i+2]-py[3*j+2];
                float dp = sqrtf(ex*ex + ey*ey + ez*ez);
                float tr = dg - dp;
                cnt += 1.0f; ss += sig2; st += tr * tr;
            }
        }
        #pragma unroll
        for (int off = 16; off; off >>= 1) {
            cnt += __shfl_down_sync(FULL, cnt, off);
            ss  += __shfl_down_sync(FULL, ss,  off);
            st  += __shfl_down_sync(FULL, st,  off);
        }
        if (tid == 0) {
            float mvar = sqrtf(ss / cnt);
            float rmse = sqrtf(st / cnt);
            out[0] = fabsf(mvar - rmse) / mvar;
        }
        return;
    }

    // degenerate fallback: exact all-pairs
    {
        float cnt = 0.0f, ss = 0.0f, st = 0.0f;
        long total = (long)N * (long)N;
        for (long p = tid; p < total; p += GNT) {
            int i = (int)(p / N), j = (int)(p - (long)i * N);
            if (i == j) continue;
            float sig2 = sig2_of_sum(__ldg(sigmas + i) + __ldg(sigmas + j));
            float t = (sig2 - begin) / interval;
            int bi = (int)floorf(t);
            bi = bi < 0 ? 0 : (bi > 9 ? 9 : bi);
            if (bi == 9) {
                float dx = y[3*i]-y[3*j], dy = y[3*i+1]-y[3*j+1], dz = y[3*i+2]-y[3*j+2];
                float dg = sqrtf(dx*dx + dy*dy + dz*dz);
                float ex = py[3*i]-py[3*j], ey = py[3*i+1]-py[3*j+1], ez = py[3*i+2]-py[3*j+2];
                float dp = sqrtf(ex*ex + ey*ey + ez*ez);
                float tr = dg - dp;
                cnt += 1.0f; ss += sig2; st += tr * tr;
            }
        }
        #pragma unroll
        for (int off = 16; off; off >>= 1) {
            cnt += __shfl_down_sync(FULL, cnt, off);
            ss  += __shfl_down_sync(FULL, ss,  off);
            st  += __shfl_down_sync(FULL, st,  off);
        }
        if ((tid & 31) == 0) { red[tid>>5][0]=cnt; red[tid>>5][1]=ss; red[tid>>5][2]=st; }
        __syncthreads();
        if (tid < 32) {
            cnt = red[tid][0]; ss = red[tid][1]; st = red[tid][2];
            #pragma unroll
            for (int off = 16; off; off >>= 1) {
                cnt += __shfl_down_sync(FULL, cnt, off);
                ss  += __shfl_down_sync(FULL, ss,  off);
                st  += __shfl_down_sync(FULL, st,  off);
            }
            if (tid == 0) {
                float mvar = sqrtf(ss / cnt);
                float rmse = sqrtf(st / cnt);
                out[0] = fabsf(mvar - rmse) / mvar;
            }
        }
    }
}

extern "C" void kernel_launch(void* const* d_in, const int* in_sizes, int n_in,
                              void* d_out, int out_size) {
    const float* sigmas = (const float*)d_in[0];
    const float* y      = (const float*)d_in[1];
    const float* py     = (const float*)d_in[2];
    int N = in_sizes[0];
    if (N <= NT * EPT)
        ENCELDDT_fast<<<1, NT>>>(sigmas, y, py, (float*)d_out, N);
    else
        ENCELDDT_generic<<<1, GNT>>>(sigmas, y, py, (float*)d_out, N);
}

// round 4
// speedup vs baseline: 1.4337x; 1.2330x over previous
#include <cuda_runtime.h>
#include <math.h>
#include <float.h>

#define NT    256
#define EPT   16          // elements per thread (fast path covers N <= NT*EPT = 4096)
#define MAXK  128
#define GNT   1024        // generic-path threads
#define NWARP (NT/32)

// Exactly replicates the reference's per-element float32 computation:
//   avg = s/200 ; sig = sqrt(-2/log(1-avg^2)) ; sig2 = sig^2  (sqrt-then-square!)
__device__ __forceinline__ float sig2_of_sum(float s) {
    float avg = s / 200.0f;
    float l   = logf(1.0f - avg * avg);
    float v   = -2.0f / l;
    float sg  = sqrtf(v);
    return sg * sg;
}

// Order-preserving float->uint encoding (total order, incl. negatives)
__device__ __forceinline__ unsigned fenc(float f) {
    unsigned u = __float_as_uint(f);
    return u ^ ((u >> 31) ? 0xFFFFFFFFu : 0x80000000u);
}
__device__ __forceinline__ float fdec(unsigned e) {
    unsigned u = (e & 0x80000000u) ? (e ^ 0x80000000u) : ~e;
    return __uint_as_float(u);
}

// merge (a1<=a2) with (b1<=b2) -> two smallest, in place
__device__ __forceinline__ void mrg2min(float& a1, float& a2, float b1, float b2) {
    float n1 = fminf(a1, b1);
    float n2 = fminf(fmaxf(a1, b1), fminf(a2, b2));
    a1 = n1; a2 = n2;
}
// merge (a1>=a2) with (b1>=b2) -> two largest, in place
__device__ __forceinline__ void mrg2max(float& a1, float& a2, float b1, float b2) {
    float n1 = fmaxf(a1, b1);
    float n2 = fmaxf(fminf(a1, b1), fmaxf(a2, b2));
    a1 = n1; a2 = n2;
}

// Warp-wide "two smallest" from per-lane sorted (e1<=e2), encoded uints.
// Returns (g1,g2) in ALL lanes. mask must be full warp.
__device__ __forceinline__ void warp2min(unsigned e1, unsigned e2,
                                         unsigned& g1, unsigned& g2) {
    const unsigned FULL = 0xFFFFFFFFu;
    g1 = __reduce_min_sync(FULL, e1);
    unsigned bal = __ballot_sync(FULL, e1 == g1);
    int leader = __ffs(bal) - 1;
    unsigned w = ((int)(threadIdx.x & 31) == leader) ? e2 : e1;
    g2 = __reduce_min_sync(FULL, w);
}
__device__ __forceinline__ void warp2max(unsigned e1, unsigned e2,
                                         unsigned& g1, unsigned& g2) {
    const unsigned FULL = 0xFFFFFFFFu;
    g1 = __reduce_max_sync(FULL, e1);
    unsigned bal = __ballot_sync(FULL, e1 == g1);
    int leader = __ffs(bal) - 1;
    unsigned w = ((int)(threadIdx.x & 31) == leader) ? e2 : e1;
    g2 = __reduce_max_sync(FULL, w);
}

// Conservative per-index sigma threshold for bin-9 candidacy.
__device__ __forceinline__ float make_sigth(float begin, float interval, float m1) {
    float th = (begin + 9.0f * interval) * 0.999f;       // conservative margin
    if (th > 0.0f && interval > 0.0f) {
        float u     = -expm1f(-2.0f / th);               // 1 - exp(-2/th)
        float avg_b = sqrtf(fmaxf(u, 0.0f)) * 1.002f;
        float sum_b = avg_b * 200.0f + 0.01f;            // loose sum bound
        return sum_b - m1;                               // per-index bound
    }
    return FLT_MAX;                                      // degenerate: admit all
}

// ============================ FAST PATH (N <= NT*EPT) ============================
__global__ __launch_bounds__(NT, 1)
void ENCELDDT_fast(const float* __restrict__ sigmas,
                   const float* __restrict__ y,
                   const float* __restrict__ py,
                   float* __restrict__ out, int N)
{
    __shared__ unsigned red[NWARP][4];           // per-warp encoded (m1,m2,M1,M2)
    __shared__ float s_begin, s_interval, s_sigth;
    __shared__ int   s_count;
    __shared__ unsigned long long s_key[MAXK];   // (idx<<32)|slot
    __shared__ int   s_ord[MAXK];                // slot in idx order
    __shared__ float s_val[MAXK];
    __shared__ float s_crd[MAXK][6];
    __shared__ float fb[NWARP][3];               // fallback reduce

    const int tid  = threadIdx.x;
    const int lane = tid & 31;
    const int wrp  = tid >> 5;
    const unsigned FULL = 0xFFFFFFFFu;
    const int base = tid * EPT;
    const bool full = (base + EPT <= N);

    if (tid == 0) s_count = 0;

    // ---- load EPT owned elements into registers (4x LDG.128 when full) ----
    float v[EPT];
    if (full) {
        #pragma unroll
        for (int q = 0; q < EPT / 4; q++) {
            float4 a = *reinterpret_cast<const float4*>(sigmas + base + 4 * q);
            v[4*q] = a.x; v[4*q+1] = a.y; v[4*q+2] = a.z; v[4*q+3] = a.w;
        }
    } else {
        #pragma unroll
        for (int k = 0; k < EPT; k++)
            v[k] = (base + k < N) ? sigmas[base + k] : 0.0f;
    }

    // ---- fire-and-forget L2 prefetch of y/py (overlaps with the crunch) ----
    {
        const char* yb  = (const char*)y;
        const char* pyb = (const char*)py;
        long ybytes = (long)N * 3 * sizeof(float);
        for (long off = (long)tid * 128; off < ybytes; off += (long)NT * 128) {
            asm volatile("prefetch.global.L2 [%0];" :: "l"(yb  + off));
            asm volatile("prefetch.global.L2 [%0];" :: "l"(pyb + off));
        }
    }

    // ---- branch-free thread-local min2/max2 via sorting-network merges ----
    float m1, m2, M1, M2;
    {
        float lo[EPT/2], hi[EPT/2];
        #pragma unroll
        for (int k = 0; k < EPT/2; k++) {
            bool va = full || (base + 2*k     < N);
            bool vb = full || (base + 2*k + 1 < N);
            float a = v[2*k], b = v[2*k+1];
            float an = va ? a :  FLT_MAX, bn = vb ? b :  FLT_MAX;
            // also need max-side with invalids as -inf; handle by separate arrays
            lo[k] = fminf(an, bn);  hi[k] = fmaxf(an, bn);
            if (!va || !vb) {                     // rare tail fix for max side
                float ax = va ? a : -FLT_MAX, bx = vb ? b : -FLT_MAX;
                // stash max-pair in place of (lo,hi) only for min; recompute max below
                (void)ax; (void)bx;
            }
        }
        // min side: merge EPT/2 ascending pairs
        float q1 = lo[0], q2 = hi[0];
        #pragma unroll
        for (int k = 1; k < EPT/2; k++) mrg2min(q1, q2, lo[k], hi[k]);
        m1 = q1; m2 = q2;
        // max side
        float go[EPT/2], gi[EPT/2];
        #pragma unroll
        for (int k = 0; k < EPT/2; k++) {
            bool va = full || (base + 2*k     < N);
            bool vb = full || (base + 2*k + 1 < N);
            float ax = va ? v[2*k]   : -FLT_MAX;
            float bx = vb ? v[2*k+1] : -FLT_MAX;
            go[k] = fmaxf(ax, bx);  gi[k] = fminf(ax, bx);
        }
        float s1 = go[0], s2 = gi[0];
        #pragma unroll
        for (int k = 1; k < EPT/2; k++) mrg2max(s1, s2, go[k], gi[k]);
        M1 = s1; M2 = s2;
    }

    // ---- warp-level merge via REDUX on encoded values ----
    unsigned wm1, wm2, wM1, wM2;
    warp2min(fenc(m1), fenc(m2), wm1, wm2);
    warp2max(fenc(M1), fenc(M2), wM1, wM2);
    if (lane == 0) {
        red[wrp][0] = wm1; red[wrp][1] = wm2;
        red[wrp][2] = wM1; red[wrp][3] = wM2;
    }
    __syncthreads();                                           // barrier 1

    if (wrp == 0) {
        unsigned e1 = (lane < NWARP) ? red[lane][0] : 0xFFFFFFFFu;
        unsigned e2 = (lane < NWARP) ? red[lane][1] : 0xFFFFFFFFu;
        unsigned f1 = (lane < NWARP) ? red[lane][2] : 0u;
        unsigned f2 = (lane < NWARP) ? red[lane][3] : 0u;
        unsigned gm1e, gm2e, gM1e, gM2e;
        warp2min(e1, e2, gm1e, gm2e);
        warp2max(f1, f2, gM1e, gM2e);
        float gm1 = fdec(gm1e), gm2 = fdec(gm2e);
        float gM1 = fdec(gM1e), gM2 = fdec(gM2e);
        // lanes 0/1 run the two log chains in parallel
        float t = sig2_of_sum((lane & 1) ? (gm1 + gm2) : (gM1 + gM2));
        float begin = __shfl_sync(FULL, t, 0);   // sig2 decreasing in sum
        float end   = __shfl_sync(FULL, t, 1);
        if (lane == 0) {
            float interval = (end - begin) / 10.0f;
            s_begin = begin; s_interval = interval;
            s_sigth = make_sigth(begin, interval, gm1);
        }
    }
    __syncthreads();                                           // barrier 2

    // ---- phase B: test registers vs threshold; gather + coord fetch (L2-warm) --
    const float sigth = s_sigth;
    #pragma unroll
    for (int k = 0; k < EPT; k++) {
        int idx = base + k;
        if (v[k] <= sigth && (full || idx < N)) {
            int p = atomicAdd(&s_count, 1);
            if (p < MAXK) {
                s_key[p] = ((unsigned long long)(unsigned)idx << 32) | (unsigned)p;
                s_val[p] = v[k];
                s_crd[p][0] = __ldg(y  + 3*idx);  s_crd[p][1] = __ldg(y  + 3*idx + 1);
                s_crd[p][2] = __ldg(y  + 3*idx + 2);
                s_crd[p][3] = __ldg(py + 3*idx);  s_crd[p][4] = __ldg(py + 3*idx + 1);
                s_crd[p][5] = __ldg(py + 3*idx + 2);
            }
        }
    }
    __syncthreads();                                           // barrier 3

    const int   K        = s_count;
    const float begin    = s_begin;
    const float interval = s_interval;

    if (K <= MAXK) {
        if (wrp != 0) return;                  // warp 0 finishes alone

        // deterministic idx-order: parallel rank sort for K<=32, serial otherwise
        if (K <= 32) {
            if (lane < K) {
                unsigned long long mine = s_key[lane];
                int rank = 0;
                for (int a = 0; a < K; a++) rank += (s_key[a] < mine) ? 1 : 0;
                s_ord[rank] = (int)(unsigned)(mine & 0xFFFFFFFFull);
            }
        } else if (lane == 0) {
            for (int a = 1; a < K; a++) {
                unsigned long long kv = s_key[a];
                int b = a - 1;
                while (b >= 0 && s_key[b] > kv) { s_key[b + 1] = s_key[b]; b--; }
                s_key[b + 1] = kv;
            }
            for (int a = 0; a < K; a++) s_ord[a] = (int)(unsigned)(s_key[a] & 0xFFFFFFFFull);
        }
        __syncwarp();

        float cnt = 0.0f, ss = 0.0f, st = 0.0f;
        int total = K * K;
        for (int p = lane; p < total; p += 32) {
            int a = p / K, b = p - a * K;
            if (a == b) continue;
            int sa = s_ord[a], sb = s_ord[b];
            float sig2 = sig2_of_sum(s_val[sa] + s_val[sb]);
            float t    = (sig2 - begin) / interval;
            int bi = (int)floorf(t);
            bi = bi < 0 ? 0 : (bi > 9 ? 9 : bi);
            if (bi == 9) {
                float dx = s_crd[sa][0] - s_crd[sb][0];
                float dy = s_crd[sa][1] - s_crd[sb][1];
                float dz = s_crd[sa][2] - s_crd[sb][2];
                float dg = sqrtf(dx*dx + dy*dy + dz*dz);
                float ex = s_crd[sa][3] - s_crd[sb][3];
                float ey = s_crd[sa][4] - s_crd[sb][4];
                float ez = s_crd[sa][5] - s_crd[sb][5];
                float dp = sqrtf(ex*ex + ey*ey + ez*ez);
                float tr = dg - dp;
                cnt += 1.0f; ss += sig2; st += tr * tr;
            }
        }
        #pragma unroll
        for (int off = 16; off; off >>= 1) {
            cnt += __shfl_down_sync(FULL, cnt, off);
            ss  += __shfl_down_sync(FULL, ss,  off);
            st  += __shfl_down_sync(FULL, st,  off);
        }
        if (lane == 0) {
            float mvar = sqrtf(ss / cnt);      // cnt >= 2: min-sum pair is bin 9
            float rmse = sqrtf(st / cnt);
            out[0] = fabsf(mvar - rmse) / mvar;
        }
        return;
    }

    // ---- degenerate fallback (K > MAXK): exact all-pairs, all threads ----
    {
        float cnt = 0.0f, ss = 0.0f, st = 0.0f;
        long total = (long)N * (long)N;
        for (long p = tid; p < total; p += NT) {
            int i = (int)(p / N), j = (int)(p - (long)i * N);
            if (i == j) continue;
            float sig2 = sig2_of_sum(__ldg(sigmas + i) + __ldg(sigmas + j));
            float t    = (sig2 - begin) / interval;
            int bi = (int)floorf(t);
            bi = bi < 0 ? 0 : (bi > 9 ? 9 : bi);
            if (bi == 9) {
                float dx = y[3*i]-y[3*j], dy = y[3*i+1]-y[3*j+1], dz = y[3*i+2]-y[3*j+2];
                float dg = sqrtf(dx*dx + dy*dy + dz*dz);
                float ex = py[3*i]-py[3*j], ey = py[3*i+1]-py[3*j+1], ez = py[3*i+2]-py[3*j+2];
                float dp = sqrtf(ex*ex + ey*ey + ez*ez);
                float tr = dg - dp;
                cnt += 1.0f; ss += sig2; st += tr * tr;
            }
        }
        #pragma unroll
        for (int off = 16; off; off >>= 1) {
            cnt += __shfl_down_sync(FULL, cnt, off);
            ss  += __shfl_down_sync(FULL, ss,  off);
            st  += __shfl_down_sync(FULL, st,  off);
        }
        if (lane == 0) { fb[wrp][0] = cnt; fb[wrp][1] = ss; fb[wrp][2] = st; }
        __syncthreads();
        if (wrp == 0) {
            cnt = (lane < NWARP) ? fb[lane][0] : 0.0f;
            ss  = (lane < NWARP) ? fb[lane][1] : 0.0f;
            st  = (lane < NWARP) ? fb[lane][2] : 0.0f;
            #pragma unroll
            for (int off = NWARP/2 > 0 ? 16 : 16; off; off >>= 1) {
                cnt += __shfl_down_sync(FULL, cnt, off);
                ss  += __shfl_down_sync(FULL, ss,  off);
                st  += __shfl_down_sync(FULL, st,  off);
            }
            if (lane == 0) {
                float mvar = sqrtf(ss / cnt);
                float rmse = sqrtf(st / cnt);
                out[0] = fabsf(mvar - rmse) / mvar;
            }
        }
    }
}

// ==================== GENERIC PATH (N > NT*EPT; strided) ====================
__device__ __forceinline__ void upd_minmax(float v, float& m1, float& m2,
                                           float& M1, float& M2) {
    if (v < m1) { m2 = m1; m1 = v; } else if (v < m2) { m2 = v; }
    if (v > M1) { M2 = M1; M1 = v; } else if (v > M2) { M2 = v; }
}

__global__ __launch_bounds__(GNT, 1)
void ENCELDDT_generic(const float* __restrict__ sigmas,
                      const float* __restrict__ y,
                      const float* __restrict__ py,
                      float* __restrict__ out, int N)
{
    __shared__ float red[32][4];
    __shared__ float s_begin, s_interval, s_sigth;
    __shared__ int   s_count;
    __shared__ unsigned long long s_key[MAXK];
    __shared__ float s_val[MAXK];

    const int tid = threadIdx.x;
    const unsigned FULL = 0xFFFFFFFFu;

    float m1 = FLT_MAX, m2 = FLT_MAX, M1 = -FLT_MAX, M2 = -FLT_MAX;
    for (int i = tid; i < N; i += GNT) upd_minmax(sigmas[i], m1, m2, M1, M2);
    #pragma unroll
    for (int off = 16; off; off >>= 1) {
        float a1 = __shfl_down_sync(FULL, m1, off);
        float a2 = __shfl_down_sync(FULL, m2, off);
        mrg2min(m1, m2, a1, a2);
        float b1 = __shfl_down_sync(FULL, M1, off);
        float b2 = __shfl_down_sync(FULL, M2, off);
        mrg2max(M1, M2, b1, b2);
    }
    if ((tid & 31) == 0) { red[tid>>5][0]=m1; red[tid>>5][1]=m2; red[tid>>5][2]=M1; red[tid>>5][3]=M2; }
    __syncthreads();
    if (tid < 32) {
        m1 = red[tid][0]; m2 = red[tid][1]; M1 = red[tid][2]; M2 = red[tid][3];
        #pragma unroll
        for (int off = 16; off; off >>= 1) {
            float a1 = __shfl_down_sync(FULL, m1, off);
            float a2 = __shfl_down_sync(FULL, m2, off);
            mrg2min(m1, m2, a1, a2);
            float b1 = __shfl_down_sync(FULL, M1, off);
            float b2 = __shfl_down_sync(FULL, M2, off);
            mrg2max(M1, M2, b1, b2);
        }
        if (tid == 0) {
            float begin    = sig2_of_sum(M1 + M2);
            float end      = sig2_of_sum(m1 + m2);
            float interval = (end - begin) / 10.0f;
            s_begin = begin; s_interval = interval;
            s_sigth = make_sigth(begin, interval, m1);
            s_count = 0;
        }
    }
    __syncthreads();

    const float sigth = s_sigth;
    for (int i = tid; i < N; i += GNT) {
        float v = sigmas[i];
        if (v <= sigth) {
            int p = atomicAdd(&s_count, 1);
            if (p < MAXK) {
                s_key[p] = ((unsigned long long)(unsigned)i << 32) | (unsigned)p;
                s_val[p] = v;
            }
        }
    }
    __syncthreads();

    const int K = s_count;
    const float begin = s_begin, interval = s_interval;

    if (K <= MAXK) {
        if (tid >= 32) return;
        if (tid == 0) {
            for (int a = 1; a < K; a++) {
                unsigned long long kv = s_key[a];
                int b = a - 1;
                while (b >= 0 && s_key[b] > kv) { s_key[b + 1] = s_key[b]; b--; }
                s_key[b + 1] = kv;
            }
        }
        __syncwarp();
        float cnt = 0.0f, ss = 0.0f, st = 0.0f;
        int total = K * K;
        for (int p = tid; p < total; p += 32) {
            int a = p / K, b = p - a * K;
            if (a == b) continue;
            int i = (int)(s_key[a] >> 32), j = (int)(s_key[b] >> 32);
            int sa = (int)(unsigned)(s_key[a] & 0xFFFFFFFFull);
            int sb = (int)(unsigned)(s_key[b] & 0xFFFFFFFFull);
            float sig2 = sig2_of_sum(s_val[sa] + s_val[sb]);
            float t = (sig2 - begin) / interval;
            int bi = (int)floorf(t);
            bi = bi < 0 ? 0 : (bi > 9 ? 9 : bi);
            if (bi == 9) {
                float dx = y[3*i]-y[3*j], dy = y[3*i+1]-y[3*j+1], dz = y[3*i+2]-y[3*j+2];
                float dg = sqrtf(dx*dx + dy*dy + dz*dz);
                float ex = py[3*i]-py[3*j], ey = py[3*i+1]-py[3*j+1], ez = py[3*i+2]-py[3*j+2];
                float dp = sqrtf(ex*ex + ey*ey + ez*ez);
                float tr = dg - dp;
                cnt += 1.0f; ss += sig2; st += tr * tr;
            }
        }
        #pragma unroll
        for (int off = 16; off; off >>= 1) {
            cnt += __shfl_down_sync(FULL, cnt, off);
            ss  += __shfl_down_sync(FULL, ss,  off);
            st  += __shfl_down_sync(FULL, st,  off);
        }
        if (tid == 0) {
            float mvar = sqrtf(ss / cnt);
            float rmse = sqrtf(st / cnt);
            out[0] = fabsf(mvar - rmse) / mvar;
        }
        return;
    }

    {   // degenerate fallback: exact all-pairs
        float cnt = 0.0f, ss = 0.0f, st = 0.0f;
        long total = (long)N * (long)N;
        for (long p = tid; p < total; p += GNT) {
            int i = (int)(p / N), j = (int)(p - (long)i * N);
            if (i == j) continue;
            float sig2 = sig2_of_sum(__ldg(sigmas + i) + __ldg(sigmas + j));
            float t = (sig2 - begin) / interval;
            int bi = (int)floorf(t);
            bi = bi < 0 ? 0 : (bi > 9 ? 9 : bi);
            if (bi == 9) {
                float dx = y[3*i]-y[3*j], dy = y[3*i+1]-y[3*j+1], dz = y[3*i+2]-y[3*j+2];
                float dg = sqrtf(dx*dx + dy*dy + dz*dz);
                float ex = py[3*i]-py[3*j], ey = py[3*i+1]-py[3*j+1], ez = py[3*i+2]-py[3*j+2];
                float dp = sqrtf(ex*ex + ey*ey + ez*ez);
                float tr = dg - dp;
                cnt += 1.0f; ss += sig2; st += tr * tr;
            }
        }
        #pragma unroll
        for (int off = 16; off; off >>= 1) {
            cnt += __shfl_down_sync(FULL, cnt, off);
            ss  += __shfl_down_sync(FULL, ss,  off);
            st  += __shfl_down_sync(FULL, st,  off);
        }
        if ((tid & 31) == 0) { red[tid>>5][0]=cnt; red[tid>>5][1]=ss; red[tid>>5][2]=st; }
        __syncthreads();
        if (tid < 32) {
            cnt = red[tid][0]; ss = red[tid][1]; st = red[tid][2];
            #pragma unroll
            for (int off = 16; off; off >>= 1) {
                cnt += __shfl_down_sync(FULL, cnt, off);
                ss  += __shfl_down_sync(FULL, ss,  off);
                st  += __shfl_down_sync(FULL, st,  off);
            }
            if (tid == 0) {
                float mvar = sqrtf(ss / cnt);
                float rmse = sqrtf(st / cnt);
                out[0] = fabsf(mvar - rmse) / mvar;
            }
        }
    }
}

extern "C" void kernel_launch(void* const* d_in, const int* in_sizes, int n_in,
                              void* d_out, int out_size) {
    const float* sigmas = (const float*)d_in[0];
    const float* y      = (const float*)d_in[1];
    const float* py     = (const float*)d_in[2];
    int N = in_sizes[0];
    if (N <= NT * EPT)
        ENCELDDT_fast<<<1, NT>>>(sigmas, y, py, (float*)d_out, N);
    else
        ENCELDDT_generic<<<1, GNT>>>(sigmas, y, py, (float*)d_out, N);
}

// round 5
// speedup vs baseline: 1.4760x; 1.0295x over previous
#include <cuda_runtime.h>
#include <math.h>
#include <float.h>

#define NT    256
#define EPT   16          // elements per thread (fast path covers N <= NT*EPT = 4096)
#define MAXK  128
#define GNT   1024        // generic-path threads
#define NWARP (NT/32)

// Exactly replicates the reference's per-element float32 computation:
//   avg = s/200 ; sig = sqrt(-2/log(1-avg^2)) ; sig2 = sig^2  (sqrt-then-square!)
__device__ __forceinline__ float sig2_of_sum(float s) {
    float avg = s / 200.0f;
    float l   = logf(1.0f - avg * avg);
    float v   = -2.0f / l;
    float sg  = sqrtf(v);
    return sg * sg;
}

// Order-preserving float->uint encoding (total order, incl. negatives)
__device__ __forceinline__ unsigned fenc(float f) {
    unsigned u = __float_as_uint(f);
    return u ^ ((u >> 31) ? 0xFFFFFFFFu : 0x80000000u);
}
__device__ __forceinline__ float fdec(unsigned e) {
    unsigned u = (e & 0x80000000u) ? (e ^ 0x80000000u) : ~e;
    return __uint_as_float(u);
}

// merge (a1<=a2) with (b1<=b2) -> two smallest, in place
__device__ __forceinline__ void mrg2min(float& a1, float& a2, float b1, float b2) {
    float n1 = fminf(a1, b1);
    float n2 = fminf(fmaxf(a1, b1), fminf(a2, b2));
    a1 = n1; a2 = n2;
}
// merge (a1>=a2) with (b1>=b2) -> two largest, in place
__device__ __forceinline__ void mrg2max(float& a1, float& a2, float b1, float b2) {
    float n1 = fmaxf(a1, b1);
    float n2 = fmaxf(fminf(a1, b1), fmaxf(a2, b2));
    a1 = n1; a2 = n2;
}

// Warp-wide "two smallest" from per-lane sorted (e1<=e2), encoded uints.
// Result in ALL lanes.
__device__ __forceinline__ void warp2min(unsigned e1, unsigned e2,
                                         unsigned& g1, unsigned& g2) {
    const unsigned FULL = 0xFFFFFFFFu;
    g1 = __reduce_min_sync(FULL, e1);
    unsigned bal = __ballot_sync(FULL, e1 == g1);
    int leader = __ffs(bal) - 1;
    unsigned w = ((int)(threadIdx.x & 31) == leader) ? e2 : e1;
    g2 = __reduce_min_sync(FULL, w);
}
__device__ __forceinline__ void warp2max(unsigned e1, unsigned e2,
                                         unsigned& g1, unsigned& g2) {
    const unsigned FULL = 0xFFFFFFFFu;
    g1 = __reduce_max_sync(FULL, e1);
    unsigned bal = __ballot_sync(FULL, e1 == g1);
    int leader = __ffs(bal) - 1;
    unsigned w = ((int)(threadIdx.x & 31) == leader) ? e2 : e1;
    g2 = __reduce_max_sync(FULL, w);
}

// Conservative per-index sigma threshold for bin-9 candidacy.
__device__ __forceinline__ float make_sigth(float begin, float interval, float m1) {
    float th = (begin + 9.0f * interval) * 0.999f;       // conservative margin
    if (th > 0.0f && interval > 0.0f) {
        float u     = -expm1f(-2.0f / th);               // 1 - exp(-2/th)
        float avg_b = sqrtf(fmaxf(u, 0.0f)) * 1.002f;
        float sum_b = avg_b * 200.0f + 0.01f;            // loose sum bound
        return sum_b - m1;                               // per-index bound
    }
    return FLT_MAX;                                      // degenerate: admit all
}

// ============================ FAST PATH (N <= NT*EPT) ============================
__global__ __launch_bounds__(NT, 1)
void ENCELDDT_fast(const float* __restrict__ sigmas,
                   const float* __restrict__ y,
                   const float* __restrict__ py,
                   float* __restrict__ out, int N)
{
    __shared__ unsigned red[NWARP][4];           // per-warp encoded (m1,m2,M1,M2)
    __shared__ int   s_count;
    __shared__ unsigned long long s_key[MAXK];   // (idx<<32)|slot
    __shared__ int   s_ord[MAXK];                // slot in idx order
    __shared__ float s_val[MAXK];
    __shared__ float s_crd[MAXK][6];
    __shared__ float fb[NWARP][3];               // degenerate-path reduce

    const int tid  = threadIdx.x;
    const int lane = tid & 31;
    const int wrp  = tid >> 5;
    const unsigned FULL = 0xFFFFFFFFu;
    const int base = tid * EPT;
    const bool full = (base + EPT <= N);

    if (tid == 0) s_count = 0;

    // ---- load EPT owned elements into registers (4x LDG.128 when full) ----
    float v[EPT];
    if (full) {
        #pragma unroll
        for (int q = 0; q < EPT / 4; q++) {
            float4 a = *reinterpret_cast<const float4*>(sigmas + base + 4 * q);
            v[4*q] = a.x; v[4*q+1] = a.y; v[4*q+2] = a.z; v[4*q+3] = a.w;
        }
    } else {
        #pragma unroll
        for (int k = 0; k < EPT; k++)
            v[k] = (base + k < N) ? sigmas[base + k] : 0.0f;
    }

    // ---- fire-and-forget L2 prefetch of y/py (covers cold-L2 replays) ----
    {
        const char* yb  = (const char*)y;
        const char* pyb = (const char*)py;
        long ybytes = (long)N * 3 * sizeof(float);
        for (long off = (long)tid * 128; off < ybytes; off += (long)NT * 128) {
            asm volatile("prefetch.global.L2 [%0];" :: "l"(yb  + off));
            asm volatile("prefetch.global.L2 [%0];" :: "l"(pyb + off));
        }
    }

    // ---- thread-local min2/max2: ONE pair-sort layer feeds both merge trees ----
    float m1, m2, M1, M2;
    if (full) {
        float lo[EPT/2], hi[EPT/2];
        #pragma unroll
        for (int k = 0; k < EPT/2; k++) {
            lo[k] = fminf(v[2*k], v[2*k+1]);
            hi[k] = fmaxf(v[2*k], v[2*k+1]);
        }
        float q1 = lo[0], q2 = hi[0];               // ascending pair
        float s1 = hi[0], s2 = lo[0];               // descending pair
        #pragma unroll
        for (int k = 1; k < EPT/2; k++) {
            mrg2min(q1, q2, lo[k], hi[k]);
            mrg2max(s1, s2, hi[k], lo[k]);
        }
        m1 = q1; m2 = q2; M1 = s1; M2 = s2;
    } else {
        float q1 = FLT_MAX, q2 = FLT_MAX, s1 = -FLT_MAX, s2 = -FLT_MAX;
        #pragma unroll
        for (int k = 0; k < EPT; k++) {
            if (base + k < N) {
                float a = v[k];
                mrg2min(q1, q2, a, FLT_MAX);
                mrg2max(s1, s2, a, -FLT_MAX);
            }
        }
        m1 = q1; m2 = q2; M1 = s1; M2 = s2;
    }

    // ---- warp-level merge via REDUX on encoded values ----
    unsigned wm1, wm2, wM1, wM2;
    warp2min(fenc(m1), fenc(m2), wm1, wm2);
    warp2max(fenc(M1), fenc(M2), wM1, wM2);
    if (lane == 0) {
        red[wrp][0] = wm1; red[wrp][1] = wm2;
        red[wrp][2] = wM1; red[wrp][3] = wM2;
    }
    __syncthreads();                                           // barrier 1 (of 2)

    // ---- EVERY warp redundantly merges + computes thresholds (no 2nd barrier) --
    float begin, interval, sigth;
    {
        unsigned e1 = (lane < NWARP) ? red[lane][0] : 0xFFFFFFFFu;
        unsigned e2 = (lane < NWARP) ? red[lane][1] : 0xFFFFFFFFu;
        unsigned f1 = (lane < NWARP) ? red[lane][2] : 0u;
        unsigned f2 = (lane < NWARP) ? red[lane][3] : 0u;
        unsigned gm1e, gm2e, gM1e, gM2e;
        warp2min(e1, e2, gm1e, gm2e);
        warp2max(f1, f2, gM1e, gM2e);
        float gm1 = fdec(gm1e), gm2 = fdec(gm2e);
        float gM1 = fdec(gM1e), gM2 = fdec(gM2e);
        // lanes 0/1 of each warp run the two log chains in parallel
        float t = sig2_of_sum((lane & 1) ? (gm1 + gm2) : (gM1 + gM2));
        begin    = __shfl_sync(FULL, t, 0);        // sig2 decreasing in sum
        float end = __shfl_sync(FULL, t, 1);
        interval = (end - begin) / 10.0f;
        sigth    = make_sigth(begin, interval, gm1);   // all lanes, identical
    }

    // ---- phase B: test registers vs threshold; gather + coord fetch ----
    #pragma unroll
    for (int k = 0; k < EPT; k++) {
        int idx = base + k;
        if (v[k] <= sigth && (full || idx < N)) {
            int p = atomicAdd(&s_count, 1);
            if (p < MAXK) {
                s_key[p] = ((unsigned long long)(unsigned)idx << 32) | (unsigned)p;
                s_val[p] = v[k];
                s_crd[p][0] = __ldg(y  + 3*idx);  s_crd[p][1] = __ldg(y  + 3*idx + 1);
                s_crd[p][2] = __ldg(y  + 3*idx + 2);
                s_crd[p][3] = __ldg(py + 3*idx);  s_crd[p][4] = __ldg(py + 3*idx + 1);
                s_crd[p][5] = __ldg(py + 3*idx + 2);
            }
        }
    }
    __syncthreads();                                           // barrier 2 (of 2)

    const int K = s_count;

    if (K <= MAXK) {
        if (wrp != 0) return;                  // warp 0 finishes alone

        // deterministic idx-order: parallel rank sort for K<=32, serial otherwise
        if (K <= 32) {
            if (lane < K) {
                unsigned long long mine = s_key[lane];
                int rank = 0;
                for (int a = 0; a < K; a++) rank += (s_key[a] < mine) ? 1 : 0;
                s_ord[rank] = (int)(unsigned)(mine & 0xFFFFFFFFull);
            }
        } else if (lane == 0) {
            for (int a = 1; a < K; a++) {
                unsigned long long kv = s_key[a];
                int b = a - 1;
                while (b >= 0 && s_key[b] > kv) { s_key[b + 1] = s_key[b]; b--; }
                s_key[b + 1] = kv;
            }
            for (int a = 0; a < K; a++) s_ord[a] = (int)(unsigned)(s_key[a] & 0xFFFFFFFFull);
        }
        __syncwarp();

        float cnt = 0.0f, ss = 0.0f, st = 0.0f;
        int total = K * K;
        for (int p = lane; p < total; p += 32) {
            int a = p / K, b = p - a * K;
            if (a == b) continue;
            int sa = s_ord[a], sb = s_ord[b];
            float sig2 = sig2_of_sum(s_val[sa] + s_val[sb]);
            float t    = (sig2 - begin) / interval;
            int bi = (int)floorf(t);
            bi = bi < 0 ? 0 : (bi > 9 ? 9 : bi);
            if (bi == 9) {
                float dx = s_crd[sa][0] - s_crd[sb][0];
                float dy = s_crd[sa][1] - s_crd[sb][1];
                float dz = s_crd[sa][2] - s_crd[sb][2];
                float dg = sqrtf(dx*dx + dy*dy + dz*dz);
                float ex = s_crd[sa][3] - s_crd[sb][3];
                float ey = s_crd[sa][4] - s_crd[sb][4];
                float ez = s_crd[sa][5] - s_crd[sb][5];
                float dp = sqrtf(ex*ex + ey*ey + ez*ez);
                float tr = dg - dp;
                cnt += 1.0f; ss += sig2; st += tr * tr;
            }
        }
        #pragma unroll
        for (int off = 16; off; off >>= 1) {
            cnt += __shfl_down_sync(FULL, cnt, off);
            ss  += __shfl_down_sync(FULL, ss,  off);
            st  += __shfl_down_sync(FULL, st,  off);
        }
        if (lane == 0) {
            float mvar = sqrtf(ss / cnt);      // cnt >= 2: min-sum pair is bin 9
            float rmse = sqrtf(st / cnt);
            out[0] = fabsf(mvar - rmse) / mvar;
        }
        return;
    }

    // ---- degenerate fallback (K > MAXK): exact all-pairs, all threads ----
    {
        float cnt = 0.0f, ss = 0.0f, st = 0.0f;
        long total = (long)N * (long)N;
        for (long p = tid; p < total; p += NT) {
            int i = (int)(p / N), j = (int)(p - (long)i * N);
            if (i == j) continue;
            float sig2 = sig2_of_sum(__ldg(sigmas + i) + __ldg(sigmas + j));
            float t    = (sig2 - begin) / interval;
            int bi = (int)floorf(t);
            bi = bi < 0 ? 0 : (bi > 9 ? 9 : bi);
            if (bi == 9) {
                float dx = y[3*i]-y[3*j], dy = y[3*i+1]-y[3*j+1], dz = y[3*i+2]-y[3*j+2];
                float dg = sqrtf(dx*dx + dy*dy + dz*dz);
                float ex = py[3*i]-py[3*j], ey = py[3*i+1]-py[3*j+1], ez = py[3*i+2]-py[3*j+2];
                float dp = sqrtf(ex*ex + ey*ey + ez*ez);
                float tr = dg - dp;
                cnt += 1.0f; ss += sig2; st += tr * tr;
            }
        }
        #pragma unroll
        for (int off = 16; off; off >>= 1) {
            cnt += __shfl_down_sync(FULL, cnt, off);
            ss  += __shfl_down_sync(FULL, ss,  off);
            st  += __shfl_down_sync(FULL, st,  off);
        }
        if (lane == 0) { fb[wrp][0] = cnt; fb[wrp][1] = ss; fb[wrp][2] = st; }
        __syncthreads();
        if (wrp == 0) {
            cnt = (lane < NWARP) ? fb[lane][0] : 0.0f;
            ss  = (lane < NWARP) ? fb[lane][1] : 0.0f;
            st  = (lane < NWARP) ? fb[lane][2] : 0.0f;
            #pragma unroll
            for (int off = 16; off; off >>= 1) {
                cnt += __shfl_down_sync(FULL, cnt, off);
                ss  += __shfl_down_sync(FULL, ss,  off);
                st  += __shfl_down_sync(FULL, st,  off);
            }
            if (lane == 0) {
                float mvar = sqrtf(ss / cnt);
                float rmse = sqrtf(st / cnt);
                out[0] = fabsf(mvar - rmse) / mvar;
            }
        }
    }
}

// ==================== GENERIC PATH (N > NT*EPT; strided) ====================
__device__ __forceinline__ void upd_minmax(float v, float& m1, float& m2,
                                           float& M1, float& M2) {
    if (v < m1) { m2 = m1; m1 = v; } else if (v < m2) { m2 = v; }
    if (v > M1) { M2 = M1; M1 = v; } else if (v > M2) { M2 = v; }
}

__global__ __launch_bounds__(GNT, 1)
void ENCELDDT_generic(const float* __restrict__ sigmas,
                      const float* __restrict__ y,
                      const float* __restrict__ py,
                      float* __restrict__ out, int N)
{
    __shared__ float red[32][4];
    __shared__ float s_begin, s_interval, s_sigth;
    __shared__ int   s_count;
    __shared__ unsigned long long s_key[MAXK];
    __shared__ float s_val[MAXK];

    const int tid = threadIdx.x;
    const unsigned FULL = 0xFFFFFFFFu;

    float m1 = FLT_MAX, m2 = FLT_MAX, M1 = -FLT_MAX, M2 = -FLT_MAX;
    for (int i = tid; i < N; i += GNT) upd_minmax(sigmas[i], m1, m2, M1, M2);
    #pragma unroll
    for (int off = 16; off; off >>= 1) {
        float a1 = __shfl_down_sync(FULL, m1, off);
        float a2 = __shfl_down_sync(FULL, m2, off);
        mrg2min(m1, m2, a1, a2);
        float b1 = __shfl_down_sync(FULL, M1, off);
        float b2 = __shfl_down_sync(FULL, M2, off);
        mrg2max(M1, M2, b1, b2);
    }
    if ((tid & 31) == 0) { red[tid>>5][0]=m1; red[tid>>5][1]=m2; red[tid>>5][2]=M1; red[tid>>5][3]=M2; }
    __syncthreads();
    if (tid < 32) {
        m1 = red[tid][0]; m2 = red[tid][1]; M1 = red[tid][2]; M2 = red[tid][3];
        #pragma unroll
        for (int off = 16; off; off >>= 1) {
            float a1 = __shfl_down_sync(FULL, m1, off);
            float a2 = __shfl_down_sync(FULL, m2, off);
            mrg2min(m1, m2, a1, a2);
            float b1 = __shfl_down_sync(FULL, M1, off);
            float b2 = __shfl_down_sync(FULL, M2, off);
            mrg2max(M1, M2, b1, b2);
        }
        if (tid == 0) {
            float begin    = sig2_of_sum(M1 + M2);
            float end      = sig2_of_sum(m1 + m2);
            float interval = (end - begin) / 10.0f;
            s_begin = begin; s_interval = interval;
            s_sigth = make_sigth(begin, interval, m1);
            s_count = 0;
        }
    }
    __syncthreads();

    const float sigth = s_sigth;
    for (int i = tid; i < N; i += GNT) {
        float v = sigmas[i];
        if (v <= sigth) {
            int p = atomicAdd(&s_count, 1);
            if (p < MAXK) {
                s_key[p] = ((unsigned long long)(unsigned)i << 32) | (unsigned)p;
                s_val[p] = v;
            }
        }
    }
    __syncthreads();

    const int K = s_count;
    const float begin = s_begin, interval = s_interval;

    if (K <= MAXK) {
        if (tid >= 32) return;
        if (tid == 0) {
            for (int a = 1; a < K; a++) {
                unsigned long long kv = s_key[a];
                int b = a - 1;
                while (b >= 0 && s_key[b] > kv) { s_key[b + 1] = s_key[b]; b--; }
                s_key[b + 1] = kv;
            }
        }
        __syncwarp();
        float cnt = 0.0f, ss = 0.0f, st = 0.0f;
        int total = K * K;
        for (int p = tid; p < total; p += 32) {
            int a = p / K, b = p - a * K;
            if (a == b) continue;
            int i = (int)(s_key[a] >> 32), j = (int)(s_key[b] >> 32);
            int sa = (int)(unsigned)(s_key[a] & 0xFFFFFFFFull);
            int sb = (int)(unsigned)(s_key[b] & 0xFFFFFFFFull);
            float sig2 = sig2_of_sum(s_val[sa] + s_val[sb]);
            float t = (sig2 - begin) / interval;
            int bi = (int)floorf(t);
            bi = bi < 0 ? 0 : (bi > 9 ? 9 : bi);
            if (bi == 9) {
                float dx = y[3*i]-y[3*j], dy = y[3*i+1]-y[3*j+1], dz = y[3*i+2]-y[3*j+2];
                float dg = sqrtf(dx*dx + dy*dy + dz*dz);
                float ex = py[3*i]-py[3*j], ey = py[3*i+1]-py[3*j+1], ez = py[3*i+2]-py[3*j+2];
                float dp = sqrtf(ex*ex + ey*ey + ez*ez);
                float tr = dg - dp;
                cnt += 1.0f; ss += sig2; st += tr * tr;
            }
        }
        #pragma unroll
        for (int off = 16; off; off >>= 1) {
            cnt += __shfl_down_sync(FULL, cnt, off);
            ss  += __shfl_down_sync(FULL, ss,  off);
            st  += __shfl_down_sync(FULL, st,  off);
        }
        if (tid == 0) {
            float mvar = sqrtf(ss / cnt);
            float rmse = sqrtf(st / cnt);
            out[0] = fabsf(mvar - rmse) / mvar;
        }
        return;
    }

    {   // degenerate fallback: exact all-pairs
        float cnt = 0.0f, ss = 0.0f, st = 0.0f;
        long total = (long)N * (long)N;
        for (long p = tid; p < total; p += GNT) {
            int i = (int)(p / N), j = (int)(p - (long)i * N);
            if (i == j) continue;
            float sig2 = sig2_of_sum(__ldg(sigmas + i) + __ldg(sigmas + j));
            float t = (sig2 - begin) / interval;
            int bi = (int)floorf(t);
            bi = bi < 0 ? 0 : (bi > 9 ? 9 : bi);
            if (bi == 9) {
                float dx = y[3*i]-y[3*j], dy = y[3*i+1]-y[3*j+1], dz = y[3*i+2]-y[3*j+2];
                float dg = sqrtf(dx*dx + dy*dy + dz*dz);
                float ex = py[3*i]-py[3*j], ey = py[3*i+1]-py[3*j+1], ez = py[3*i+2]-py[3*j+2];
                float dp = sqrtf(ex*ex + ey*ey + ez*ez);
                float tr = dg - dp;
                cnt += 1.0f; ss += sig2; st += tr * tr;
            }
        }
        #pragma unroll
        for (int off = 16; off; off >>= 1) {
            cnt += __shfl_down_sync(FULL, cnt, off);
            ss  += __shfl_down_sync(FULL, ss,  off);
            st  += __shfl_down_sync(FULL, st,  off);
        }
        if ((tid & 31) == 0) { red[tid>>5][0]=cnt; red[tid>>5][1]=ss; red[tid>>5][2]=st; }
        __syncthreads();
        if (tid < 32) {
            cnt = red[tid][0]; ss = red[tid][1]; st = red[tid][2];
            #pragma unroll
            for (int off = 16; off; off >>= 1) {
                cnt += __shfl_down_sync(FULL, cnt, off);
                ss  += __shfl_down_sync(FULL, ss,  off);
                st  += __shfl_down_sync(FULL, st,  off);
            }
            if (tid == 0) {
                float mvar = sqrtf(ss / cnt);
                float rmse = sqrtf(st / cnt);
                out[0] = fabsf(mvar - rmse) / mvar;
            }
        }
    }
}

extern "C" void kernel_launch(void* const* d_in, const int* in_sizes, int n_in,
                              void* d_out, int out_size) {
    const float* sigmas = (const float*)d_in[0];
    const float* y      = (const float*)d_in[1];
    const float* py     = (const float*)d_in[2];
    int N = in_sizes[0];
    if (N <= NT * EPT)
        ENCELDDT_fast<<<1, NT>>>(sigmas, y, py, (float*)d_out, N);
    else
        ENCELDDT_generic<<<1, GNT>>>(sigmas, y, py, (float*)d_out, N);
}